// round 14
// baseline (speedup 1.0000x reference)
#include <cuda_runtime.h>
#include <math.h>

#define BB 32
#define SS 512
#define HH 768
#define G4 3072
#define TT 9
#define VV 30522
#define MTOT (BB*SS)       // 16384
#define HT_STRIDE (HH*BB)  // 24576 floats per timestep

typedef unsigned long long u64;

// packed fp32x2 ops (sm_103a FFMA2)
#define FMA_F32X2(d, a, b, c) \
    asm("fma.rn.f32x2 %0, %1, %2, %3;" : "=l"(d) : "l"(a), "l"(b), "l"(c))
#define ADD_F32X2(d, a, b) \
    asm("add.rn.f32x2 %0, %1, %2;" : "=l"(d) : "l"(a), "l"(b))
#define PACK_F32X2(out, lo, hi) \
    asm("mov.b64 %0, {%1, %2};" : "=l"(out) : "f"(lo), "f"(hi))
#define UNPACK_F32X2(lo, hi, in) \
    asm("mov.b64 {%0, %1}, %2;" : "=f"(lo), "=f"(hi) : "l"(in))

// ---------------- scratch (device globals; no cudaMalloc allowed) ----------------
__device__ float g_gates[(size_t)MTOT * G4];   // [n][3072] sgemm output (x-part + biases)
__device__ float g_gT[(size_t)MTOT * G4];      // [t][g][j][b] transposed preacts
__device__ float g_h0[(size_t)MTOT * HH];      // layer0 hidden outputs [b*S+t][H]
__device__ float g_h1[(size_t)MTOT * HH];      // layer1 hidden outputs
__device__ float g_hT[(size_t)SS * HT_STRIDE]; // transposed hidden [t][j][b]
__device__ float g_wpack[4 * 384 * 768 * 2];   // [g][jpair][k][(j0,j1)]
__device__ float g_logp[MTOT * TT];            // log-softmax emissions
__device__ int   g_ids[MTOT];
__device__ int   g_labels[MTOT];
__device__ float g_llh[BB];
__device__ int   g_lenbuf[BB];
__device__ volatile unsigned g_flags[128 * 32]; // per-block step flags, 128B apart

// ---------------- int64/int32 auto-detect + convert (with clamping) ----------------
__global__ void convert_idx_k(const void* __restrict__ idsraw, const void* __restrict__ labraw) {
    int i = blockIdx.x * blockDim.x + threadIdx.x;
    const unsigned* w = (const unsigned*)idsraw;
    bool is64 = true;
#pragma unroll
    for (int k = 0; k < 16; k++) is64 = is64 && (w[2 * k + 1] == 0u);
    if (i < MTOT) {
        long long idv, lbv;
        if (is64) {
            idv = ((const long long*)idsraw)[i];
            lbv = ((const long long*)labraw)[i];
        } else {
            idv = ((const int*)idsraw)[i];
            lbv = ((const int*)labraw)[i];
        }
        int idi = (int)idv, lbi = (int)lbv;
        if (idi < 0) idi = 0; if (idi >= VV) idi = VV - 1;
        if (lbi < 0) lbi = 0; if (lbi >= TT) lbi = TT - 1;
        g_ids[i] = idi;
        g_labels[i] = lbi;
    }
}

__global__ void reset_bar_k() {
    if (threadIdx.x < 128) g_flags[threadIdx.x * 32] = 0u;
}

// ---------------- pack Whh -> [g][jpair][k][(j0,j1)] ----------------
__global__ void pack_whh_k(const float* __restrict__ Whh, float* __restrict__ wp) {
    int i = blockIdx.x * 256 + threadIdx.x;
    if (i < 4 * 384 * 768 * 2) {
        int s = i & 1;
        int k = (i >> 1) % 768;
        int jp = ((i >> 1) / 768) % 384;
        int g = i / (768 * 2 * 384);
        wp[i] = Whh[((size_t)(g * 768 + jp * 2 + s)) * 768 + k];
    }
}

// ---------------- transpose gates [n][col] -> gT[t][g][j][b] ----------------
__global__ __launch_bounds__(256) void transpose_gates_k(
    const float* __restrict__ gates, float* __restrict__ gT)
{
    __shared__ float sm[32 * 33];
    const int jt = blockIdx.x;    // 0..23
    const int g  = blockIdx.y;    // 0..3
    const int t  = blockIdx.z;    // 0..511
    const int wi = threadIdx.x >> 5, lane = threadIdx.x & 31;
#pragma unroll
    for (int r = 0; r < 4; r++) {
        int b = wi + r * 8;
        float v = gates[((size_t)(b * SS + t)) * G4 + g * HH + jt * 32 + lane];
        sm[lane * 33 + b] = v;   // sm[j_local][b]
    }
    __syncthreads();
#pragma unroll
    for (int r = 0; r < 4; r++) {
        int jrow = wi + r * 8;
        gT[(((size_t)t * 4 + g) * HH + jt * 32 + jrow) * 32 + lane] = sm[jrow * 33 + lane];
    }
}

// ---------------- SGEMM (f32x2): C[M,3072] = A[M,768] @ W[3072,768]^T + (b1+b2) ----------------
__global__ __launch_bounds__(256) void sgemm_gate_k(
    const float* __restrict__ A, int use_gather,
    const float* __restrict__ W,
    const float* __restrict__ b1, const float* __restrict__ b2,
    float* __restrict__ C)
{
    __shared__ float As[16][132];
    __shared__ float Bs[16][64];
    const int bn = blockIdx.x;
    const int bm = blockIdx.y;
    const int tid = threadIdx.x;
    const int tm = tid >> 4, tn = tid & 15;
    const int row0 = bm * 128;

    const int ar = tid >> 1;
    const int akk = (tid & 1) * 8;
    int grow = row0 + ar;
    if (use_gather) grow = g_ids[grow];
    const float* arow = A + (size_t)grow * HH;
    const int br = tid >> 2;
    const int bkk = (tid & 3) * 4;
    const float* wrow = W + (size_t)(bn * 64 + br) * HH + bkk;

    u64 acc2[4][4];
#pragma unroll
    for (int p = 0; p < 4; p++)
#pragma unroll
        for (int q = 0; q < 4; q++) acc2[p][q] = 0ull;

    for (int k0 = 0; k0 < HH; k0 += 16) {
        float4 a0 = *(const float4*)(arow + k0 + akk);
        float4 a1 = *(const float4*)(arow + k0 + akk + 4);
        float4 bv = *(const float4*)(wrow + k0);
        As[akk + 0][ar] = a0.x; As[akk + 1][ar] = a0.y; As[akk + 2][ar] = a0.z; As[akk + 3][ar] = a0.w;
        As[akk + 4][ar] = a1.x; As[akk + 5][ar] = a1.y; As[akk + 6][ar] = a1.z; As[akk + 7][ar] = a1.w;
        Bs[bkk + 0][br] = bv.x; Bs[bkk + 1][br] = bv.y; Bs[bkk + 2][br] = bv.z; Bs[bkk + 3][br] = bv.w;
        __syncthreads();
#pragma unroll
        for (int kk = 0; kk < 16; kk++) {
            ulonglong2 av0 = *(const ulonglong2*)&As[kk][tm * 8];
            ulonglong2 av1 = *(const ulonglong2*)&As[kk][tm * 8 + 4];
            float4 y = *(const float4*)&Bs[kk][tn * 4];
            u64 ap[4] = {av0.x, av0.y, av1.x, av1.y};
            u64 bd[4];
            PACK_F32X2(bd[0], y.x, y.x);
            PACK_F32X2(bd[1], y.y, y.y);
            PACK_F32X2(bd[2], y.z, y.z);
            PACK_F32X2(bd[3], y.w, y.w);
#pragma unroll
            for (int p = 0; p < 4; p++)
#pragma unroll
                for (int q = 0; q < 4; q++)
                    FMA_F32X2(acc2[p][q], ap[p], bd[q], acc2[p][q]);
        }
        __syncthreads();
    }
    const int col = bn * 64 + tn * 4;
    float bsv[4];
#pragma unroll
    for (int q = 0; q < 4; q++) bsv[q] = b1[col + q] + b2[col + q];
#pragma unroll
    for (int p = 0; p < 4; p++) {
        float lo[4], hi[4];
#pragma unroll
        for (int q = 0; q < 4; q++) UNPACK_F32X2(lo[q], hi[q], acc2[p][q]);
        int gm0 = row0 + tm * 8 + 2 * p;
        float4 o0, o1;
        o0.x = lo[0] + bsv[0]; o0.y = lo[1] + bsv[1]; o0.z = lo[2] + bsv[2]; o0.w = lo[3] + bsv[3];
        o1.x = hi[0] + bsv[0]; o1.y = hi[1] + bsv[1]; o1.z = hi[2] + bsv[2]; o1.w = hi[3] + bsv[3];
        *(float4*)&C[(size_t)gm0 * G4 + col] = o0;
        *(float4*)&C[(size_t)(gm0 + 1) * G4 + col] = o1;
    }
}

// ---------------- Persistent LSTM layer (weights in SMEM, distributed-flag barrier) ----------------
#define WS_FLOATS (3 * 4 * 768 * 2)                // 18432 floats = 73728 B
#define HS_FLOATS (768 * 33)                       // 25344 floats = 101376 B
#define EX_QWORDS (24 * 4 * 33)                    // 3168 u64 = 25344 B
#define SMEM_LSTM_BYTES ((WS_FLOATS + HS_FLOATS) * 4 + EX_QWORDS * 8)   // 200448 B

__global__ __launch_bounds__(768) void lstm_seq_k(float* __restrict__ hT)
{
    extern __shared__ float sm[];
    float* ws = sm;                                   // [jpl][g][k][2]
    float* hs = sm + WS_FLOATS;                       // hs[k*33 + b]
    u64* exq = (u64*)(sm + WS_FLOATS + HS_FLOATS);    // exq[(w*4+g)*33 + lane]
    const int tid = threadIdx.x;
    const int w = tid >> 5, lane = tid & 31;
    const int jpl = w >> 3, ks = w & 7;
    const int k0 = ks * 96;
    const bool act = (w < 6);
    const int ja = blockIdx.x * 6 + w;            // activation j (valid if act)
    const int jpa = w >> 1, jsel = w & 1;         // activation partial source
    float c = 0.f;

    // ---- one-time weight preload into smem
    {
        const float4* src4 = (const float4*)g_wpack;
        float4* dst4 = (float4*)ws;
#pragma unroll
        for (int it = 0; it < 6; it++) {
            int i = it * 768 + tid;         // 0..4607 float4s
            int chunk = i / 384;            // 0..11 = jpl*4+g
            int q = i - chunk * 384;
            int cjpl = chunk >> 2, cg = chunk & 3;
            dst4[chunk * 384 + q] = src4[(size_t)(cg * 384 + blockIdx.x * 3 + cjpl) * 384 + q];
        }
    }
    __syncthreads();

    const float* wbase = ws + (jpl * 4) * 1536 + k0 * 2;   // gate g at +g*1536

    for (int t = 0; t < SS; t++) {
        // prefetch preactivations for activation warps (coalesced)
        float pre[4];
        if (act) {
#pragma unroll
            for (int g = 0; g < 4; g++)
                pre[g] = g_gT[(((size_t)t * 4 + g) * HH + ja) * 32 + lane];
        }

        u64 accA[4], accB[4];
#pragma unroll
        for (int g = 0; g < 4; g++) { accA[g] = 0ull; accB[g] = 0ull; }

        if (t > 0) {
            // stage h_{t-1} from hT[t-1][j][b] into hs[k=j][b] (conflict-free scatter)
            const float* src = hT + (size_t)(t - 1) * HT_STRIDE;
#pragma unroll
            for (int r = 0; r < 8; r++) {
                int idx = r * 3072 + tid * 4;
                float4 v = __ldcg((const float4*)(src + idx));
                int jj = idx >> 5, b0 = idx & 31;
                hs[jj * 33 + b0 + 0] = v.x;
                hs[jj * 33 + b0 + 1] = v.y;
                hs[jj * 33 + b0 + 2] = v.z;
                hs[jj * 33 + b0 + 3] = v.w;
            }
            __syncthreads();

            const float* hb = hs + k0 * 33 + lane;
#pragma unroll 8
            for (int kc = 0; kc < 48; kc++) {
                float h0 = hb[(2 * kc) * 33];
                float h1 = hb[(2 * kc + 1) * 33];
                u64 hp0, hp1;
                PACK_F32X2(hp0, h0, h0);
                PACK_F32X2(hp1, h1, h1);
                ulonglong2 w0 = *(const ulonglong2*)(wbase + 0 * 1536 + kc * 4);
                ulonglong2 w1 = *(const ulonglong2*)(wbase + 1 * 1536 + kc * 4);
                ulonglong2 w2 = *(const ulonglong2*)(wbase + 2 * 1536 + kc * 4);
                ulonglong2 w3 = *(const ulonglong2*)(wbase + 3 * 1536 + kc * 4);
                FMA_F32X2(accA[0], w0.x, hp0, accA[0]); FMA_F32X2(accB[0], w0.y, hp1, accB[0]);
                FMA_F32X2(accA[1], w1.x, hp0, accA[1]); FMA_F32X2(accB[1], w1.y, hp1, accB[1]);
                FMA_F32X2(accA[2], w2.x, hp0, accA[2]); FMA_F32X2(accB[2], w2.y, hp1, accB[2]);
                FMA_F32X2(accA[3], w3.x, hp0, accA[3]); FMA_F32X2(accB[3], w3.y, hp1, accB[3]);
            }
        }
        // combine + exchange
#pragma unroll
        for (int g = 0; g < 4; g++) {
            u64 pd;
            ADD_F32X2(pd, accA[g], accB[g]);
            exq[(w * 4 + g) * 33 + lane] = pd;
        }
        __syncthreads();

        if (act) {
            float gt[4];
#pragma unroll
            for (int g = 0; g < 4; g++) {
                float s = pre[g];
#pragma unroll
                for (int p = 0; p < 8; p++) {
                    u64 v = exq[(((jpa * 8 + p) * 4) + g) * 33 + lane];
                    float lo, hi;
                    UNPACK_F32X2(lo, hi, v);
                    s += jsel ? hi : lo;
                }
                gt[g] = s;
            }
            float iv = __fdividef(1.f, 1.f + __expf(-gt[0]));
            float fv = __fdividef(1.f, 1.f + __expf(-gt[1]));
            float gv = tanhf(gt[2]);
            float ov = __fdividef(1.f, 1.f + __expf(-gt[3]));
            c = fv * c + iv * gv;
            float hn = ov * tanhf(c);
            hT[(size_t)t * HT_STRIDE + ja * 32 + lane] = hn;
        }

        if (t + 1 < SS) {
            __syncthreads();   // all h stores done (CTA-scope)
            if (tid == 0) {
                __threadfence();                  // gpu-scope release (cumulative)
                g_flags[blockIdx.x * 32] = (unsigned)(t + 1);
            }
            if (tid < 128) {
                // each thread polls a DISTINCT block's flag (no hot line)
                if (g_flags[tid * 32] < (unsigned)(t + 1)) {
                    do { __nanosleep(32); } while (g_flags[tid * 32] < (unsigned)(t + 1));
                }
            }
            __syncthreads();
        }
    }
}

// ---------------- transpose g_hT[t][j][b] -> h[n=b*S+t][j] ----------------
__global__ __launch_bounds__(768) void transpose_h_k(
    const float* __restrict__ hT, float* __restrict__ hout)
{
    extern __shared__ float sm[];   // [768][33]
    const int t = blockIdx.x;
    const int tid = threadIdx.x;
#pragma unroll
    for (int r = 0; r < 32; r++) {
        int idx = r * 768 + tid;
        float v = __ldcg(hT + (size_t)t * HT_STRIDE + idx);
        sm[(idx >> 5) * 33 + (idx & 31)] = v;
    }
    __syncthreads();
#pragma unroll
    for (int b = 0; b < 32; b++) {
        hout[((size_t)(b * SS + t)) * HH + tid] = sm[tid * 33 + b];
    }
}

// ---------------- logits + log_softmax ----------------
__global__ __launch_bounds__(256) void logits_k(
    const float* __restrict__ h, const float* __restrict__ Wout, const float* __restrict__ bout)
{
    const int warp = threadIdx.x >> 5, lane = threadIdx.x & 31;
    const int n = blockIdx.x * 8 + warp;
    float a[24];
#pragma unroll
    for (int c = 0; c < 6; c++) {
        float4 v = *(const float4*)(h + (size_t)n * HH + c * 128 + lane * 4);
        a[c * 4 + 0] = v.x; a[c * 4 + 1] = v.y; a[c * 4 + 2] = v.z; a[c * 4 + 3] = v.w;
    }
    float lg[TT];
#pragma unroll
    for (int t = 0; t < TT; t++) {
        float s = 0.f;
#pragma unroll
        for (int c = 0; c < 6; c++) {
            float4 w = *(const float4*)(Wout + (size_t)t * HH + c * 128 + lane * 4);
            s = fmaf(w.x, a[c * 4 + 0], s); s = fmaf(w.y, a[c * 4 + 1], s);
            s = fmaf(w.z, a[c * 4 + 2], s); s = fmaf(w.w, a[c * 4 + 3], s);
        }
#pragma unroll
        for (int o = 16; o; o >>= 1) s += __shfl_xor_sync(0xffffffffu, s, o);
        lg[t] = s + bout[t];
    }
    float m = lg[0];
#pragma unroll
    for (int t = 1; t < TT; t++) m = fmaxf(m, lg[t]);
    float se = 0.f;
#pragma unroll
    for (int t = 0; t < TT; t++) se += expf(lg[t] - m);
    float ls = m + logf(se);
    if (lane < TT) g_logp[(size_t)n * TT + lane] = lg[lane] - ls;
}

// ---------------- CRF NLL forward (warp per batch) ----------------
__global__ __launch_bounds__(128) void crf_forward_k(
    const int* __restrict__ amask,
    const float* __restrict__ start_t, const float* __restrict__ end_t,
    const float* __restrict__ trans)
{
    __shared__ float ts[TT * TT];
    if (threadIdx.x < TT * TT) ts[threadIdx.x] = trans[threadIdx.x];
    __syncthreads();
    const int w = threadIdx.x >> 5, lane = threadIdx.x & 31;
    const int b = blockIdx.x * 4 + w;
    const int* tg = g_labels + b * SS;
    const int* mk = amask + b * SS;
    const float* em = g_logp + (size_t)b * SS * TT;

    int cnt = 0; float num = 0.f;
    for (int s = lane; s < SS; s += 32) {
        int m = mk[s]; cnt += m;
        if (s > 0 && m) num += ts[tg[s - 1] * TT + tg[s]] + em[s * TT + tg[s]];
    }
    if (lane == 0) num += start_t[tg[0]] + em[tg[0]];
#pragma unroll
    for (int o = 16; o; o >>= 1) {
        num += __shfl_xor_sync(0xffffffffu, num, o);
        cnt += __shfl_xor_sync(0xffffffffu, cnt, o);
    }
    if (lane == 0) num += end_t[tg[cnt - 1]];
    num = __shfl_sync(0xffffffffu, num, 0);

    const int j = lane;
    float score = (j < TT) ? start_t[j] + em[j] : -1e30f;
    for (int s = 1; s < SS; s++) {
        float v[TT];
#pragma unroll
        for (int i = 0; i < TT; i++) v[i] = __shfl_sync(0xffffffffu, score, i);
        if (mk[s]) {
            if (j < TT) {
                float vv[TT], m2 = -1e30f;
#pragma unroll
                for (int i = 0; i < TT; i++) { vv[i] = v[i] + ts[i * TT + j]; m2 = fmaxf(m2, vv[i]); }
                float ssum = 0.f;
#pragma unroll
                for (int i = 0; i < TT; i++) ssum += expf(vv[i] - m2);
                score = m2 + logf(ssum) + em[s * TT + j];
            }
        }
    }
    float sc2 = (j < TT) ? score + end_t[j] : -1e30f;
    float vv[TT];
#pragma unroll
    for (int i = 0; i < TT; i++) vv[i] = __shfl_sync(0xffffffffu, sc2, i);
    if (lane == 0) {
        float m2 = vv[0];
#pragma unroll
        for (int i = 1; i < TT; i++) m2 = fmaxf(m2, vv[i]);
        float ssum = 0.f;
#pragma unroll
        for (int i = 0; i < TT; i++) ssum += expf(vv[i] - m2);
        float denom = m2 + logf(ssum);
        g_llh[b] = num - denom;
        g_lenbuf[b] = cnt;
    }
}

// ---------------- Viterbi decode (warp per batch, bp in smem), float32 output ----------------
__global__ __launch_bounds__(128) void viterbi_k(
    const int* __restrict__ amask,
    const float* __restrict__ start_t, const float* __restrict__ end_t,
    const float* __restrict__ trans, float* __restrict__ outp, int navail)
{
    __shared__ float ts[TT * TT];
    __shared__ unsigned char bp[4][SS][TT];
    if (threadIdx.x < TT * TT) ts[threadIdx.x] = trans[threadIdx.x];
    __syncthreads();
    const int w = threadIdx.x >> 5, lane = threadIdx.x & 31;
    const int b = blockIdx.x * 4 + w;
    const int* mk = amask + b * SS;
    const float* em = g_logp + (size_t)b * SS * TT;
    const int j = lane;

    float score = (j < TT) ? start_t[j] + em[j] : -1e30f;
    for (int s = 1; s < SS; s++) {
        float v[TT];
#pragma unroll
        for (int i = 0; i < TT; i++) v[i] = __shfl_sync(0xffffffffu, score, i);
        if (j < TT) {
            int bi = j;
            if (mk[s]) {
                float best = v[0] + ts[0 * TT + j]; bi = 0;
#pragma unroll
                for (int i = 1; i < TT; i++) {
                    float cc = v[i] + ts[i * TT + j];
                    if (cc > best) { best = cc; bi = i; }
                }
                score = best + em[s * TT + j];
            }
            bp[w][s][j] = (unsigned char)bi;
        }
    }
    float sc2 = (j < TT) ? score + end_t[j] : -1e30f;
    float vv[TT];
#pragma unroll
    for (int i = 0; i < TT; i++) vv[i] = __shfl_sync(0xffffffffu, sc2, i);
    if (lane == 0) {
        int tag = 0; float best = vv[0];
#pragma unroll
        for (int i = 1; i < TT; i++) if (vv[i] > best) { best = vv[i]; tag = i; }
        for (int s = SS - 1; s >= 1; s--) {
            int idx = b * SS + s;
            if (idx < navail) outp[idx] = mk[s] ? (float)tag : 0.0f;
            tag = (int)bp[w][s][tag];
        }
        if (b * SS < navail) outp[b * SS] = mk[0] ? (float)tag : 0.0f;
    }
}

// ---------------- finalize loss (float32) ----------------
__global__ void finalize32_k(float* __restrict__ out) {
    const int lane = threadIdx.x;
    float llh = g_llh[lane];
    int len = g_lenbuf[lane];
#pragma unroll
    for (int o = 16; o; o >>= 1) {
        llh += __shfl_xor_sync(0xffffffffu, llh, o);
        len += __shfl_xor_sync(0xffffffffu, len, o);
    }
    if (lane == 0) out[0] = (float)(-(double)llh / (double)len);
}

// ---------------- launch ----------------
extern "C" void kernel_launch(void* const* d_in, const int* in_sizes, int n_in,
                              void* d_out, int out_size) {
    (void)in_sizes; (void)n_in;
    const void* ids    = d_in[0];
    const int*  amask  = (const int*)d_in[1];
    const void* labels = d_in[2];
    const float* emb   = (const float*)d_in[3];
    const float* Wih0  = (const float*)d_in[4];
    const float* Whh0  = (const float*)d_in[5];
    const float* bih0  = (const float*)d_in[6];
    const float* bhh0  = (const float*)d_in[7];
    const float* Wih1  = (const float*)d_in[8];
    const float* Whh1  = (const float*)d_in[9];
    const float* bih1  = (const float*)d_in[10];
    const float* bhh1  = (const float*)d_in[11];
    const float* Wout  = (const float*)d_in[12];
    const float* bout  = (const float*)d_in[13];
    const float* start_t = (const float*)d_in[14];
    const float* end_t   = (const float*)d_in[15];
    const float* trans   = (const float*)d_in[16];
    float* out = (float*)d_out;

    void *p_gates, *p_gT, *p_h0, *p_h1, *p_hT, *p_wp;
    cudaGetSymbolAddress(&p_gates, g_gates);
    cudaGetSymbolAddress(&p_gT, g_gT);
    cudaGetSymbolAddress(&p_h0, g_h0);
    cudaGetSymbolAddress(&p_h1, g_h1);
    cudaGetSymbolAddress(&p_hT, g_hT);
    cudaGetSymbolAddress(&p_wp, g_wpack);

    cudaFuncSetAttribute(lstm_seq_k, cudaFuncAttributeMaxDynamicSharedMemorySize, SMEM_LSTM_BYTES);
    const int tsm = 768 * 33 * 4;  // 101376
    cudaFuncSetAttribute(transpose_h_k, cudaFuncAttributeMaxDynamicSharedMemorySize, tsm);

    convert_idx_k<<<64, 256>>>(ids, labels);

    dim3 ggrid(48, 128);
    dim3 tggrid(24, 4, 512);
    const int packblocks = (4 * 384 * 768 * 2 + 255) / 256;

    // layer 0
    sgemm_gate_k<<<ggrid, 256>>>(emb, 1, Wih0, bih0, bhh0, (float*)p_gates);
    pack_whh_k<<<packblocks, 256>>>(Whh0, (float*)p_wp);
    transpose_gates_k<<<tggrid, 256>>>((const float*)p_gates, (float*)p_gT);
    reset_bar_k<<<1, 128>>>();
    lstm_seq_k<<<128, 768, SMEM_LSTM_BYTES>>>((float*)p_hT);
    transpose_h_k<<<512, 768, tsm>>>((const float*)p_hT, (float*)p_h0);
    // layer 1
    sgemm_gate_k<<<ggrid, 256>>>((const float*)p_h0, 0, Wih1, bih1, bhh1, (float*)p_gates);
    pack_whh_k<<<packblocks, 256>>>(Whh1, (float*)p_wp);
    transpose_gates_k<<<tggrid, 256>>>((const float*)p_gates, (float*)p_gT);
    reset_bar_k<<<1, 128>>>();
    lstm_seq_k<<<128, 768, SMEM_LSTM_BYTES>>>((float*)p_hT);
    transpose_h_k<<<512, 768, tsm>>>((const float*)p_hT, (float*)p_h1);

    logits_k<<<2048, 256>>>((const float*)p_h1, Wout, bout);
    crf_forward_k<<<8, 128>>>(amask, start_t, end_t, trans);

    if (out_size >= 1 + MTOT) {
        viterbi_k<<<8, 128>>>(amask, start_t, end_t, trans, out + 1, out_size - 1);
    }
    finalize32_k<<<1, 32>>>(out);
}

// round 15
// speedup vs baseline: 1.0428x; 1.0428x over previous
#include <cuda_runtime.h>
#include <math.h>

#define BB 32
#define SS 512
#define HH 768
#define G4 3072
#define TT 9
#define VV 30522
#define MTOT (BB*SS)       // 16384
#define HT_STRIDE (HH*BB)  // 24576 floats per timestep

typedef unsigned long long u64;

// packed fp32x2 ops (sm_103a FFMA2)
#define FMA_F32X2(d, a, b, c) \
    asm("fma.rn.f32x2 %0, %1, %2, %3;" : "=l"(d) : "l"(a), "l"(b), "l"(c))
#define ADD_F32X2(d, a, b) \
    asm("add.rn.f32x2 %0, %1, %2;" : "=l"(d) : "l"(a), "l"(b))
#define PACK_F32X2(out, lo, hi) \
    asm("mov.b64 %0, {%1, %2};" : "=l"(out) : "f"(lo), "f"(hi))
#define UNPACK_F32X2(lo, hi, in) \
    asm("mov.b64 {%0, %1}, %2;" : "=f"(lo), "=f"(hi) : "l"(in))

// ---------------- scratch (device globals; no cudaMalloc allowed) ----------------
__device__ float g_gT[(size_t)MTOT * G4];      // [t][g][j][b] gate preacts (written directly by sgemm)
__device__ float g_h0[(size_t)MTOT * HH];      // layer0 hidden, rows n' = t*32+b
__device__ float g_h1[(size_t)MTOT * HH];      // layer1 hidden, rows n' = t*32+b
__device__ float g_hT[(size_t)SS * HT_STRIDE]; // transposed hidden [t][j][b]
__device__ float g_wpack[4 * 384 * 768 * 2];   // [g][jpair][k][(j0,j1)]
__device__ float g_logp[MTOT * TT];            // log-softmax emissions, [b*S+t][tag]
__device__ int   g_ids[MTOT];
__device__ int   g_labels[MTOT];
__device__ float g_llh[BB];
__device__ int   g_lenbuf[BB];
__device__ unsigned g_bar;                     // global barrier counter (monotonic per layer)

// ---------------- int64/int32 auto-detect + convert (with clamping) ----------------
__global__ void convert_idx_k(const void* __restrict__ idsraw, const void* __restrict__ labraw) {
    int i = blockIdx.x * blockDim.x + threadIdx.x;
    const unsigned* w = (const unsigned*)idsraw;
    bool is64 = true;
#pragma unroll
    for (int k = 0; k < 16; k++) is64 = is64 && (w[2 * k + 1] == 0u);
    if (i < MTOT) {
        long long idv, lbv;
        if (is64) {
            idv = ((const long long*)idsraw)[i];
            lbv = ((const long long*)labraw)[i];
        } else {
            idv = ((const int*)idsraw)[i];
            lbv = ((const int*)labraw)[i];
        }
        int idi = (int)idv, lbi = (int)lbv;
        if (idi < 0) idi = 0; if (idi >= VV) idi = VV - 1;
        if (lbi < 0) lbi = 0; if (lbi >= TT) lbi = TT - 1;
        g_ids[i] = idi;
        g_labels[i] = lbi;
    }
}

__global__ void reset_bar_k() { g_bar = 0u; }

// ---------------- pack Whh -> [g][jpair][k][(j0,j1)] ----------------
__global__ void pack_whh_k(const float* __restrict__ Whh, float* __restrict__ wp) {
    int i = blockIdx.x * 256 + threadIdx.x;
    if (i < 4 * 384 * 768 * 2) {
        int s = i & 1;
        int k = (i >> 1) % 768;
        int jp = ((i >> 1) / 768) % 384;
        int g = i / (768 * 2 * 384);
        wp[i] = Whh[((size_t)(g * 768 + jp * 2 + s)) * 768 + k];
    }
}

// ---------------- SGEMM (f32x2), rows n' = t*32+b, epilogue writes gT[t][g][j][b] ----------------
__global__ __launch_bounds__(256) void sgemm_gate_k(
    const float* __restrict__ A, int use_gather,
    const float* __restrict__ W,
    const float* __restrict__ b1, const float* __restrict__ b2,
    float* __restrict__ gT)
{
    __shared__ float As[16][132];
    __shared__ float Bs[16][64];
    __shared__ float tbuf[128 * 65];   // [row_local][col] tile for transposed output
    const int bn = blockIdx.x;         // 0..47 col tile (64 cols)
    const int bm = blockIdx.y;         // 0..127 row tile (128 rows = 4 t x 32 b)
    const int tid = threadIdx.x;
    const int tm = tid >> 4, tn = tid & 15;
    const int row0 = bm * 128;

    const int ar = tid >> 1;
    const int akk = (tid & 1) * 8;
    int grow = row0 + ar;              // n' = t*32 + b
    const float* arow;
    if (use_gather) {
        int id = g_ids[(grow & 31) * SS + (grow >> 5)];
        arow = A + (size_t)id * HH;
    } else {
        arow = A + (size_t)grow * HH;
    }
    const int br = tid >> 2;
    const int bkk = (tid & 3) * 4;
    const float* wrow = W + (size_t)(bn * 64 + br) * HH + bkk;

    u64 acc2[4][4];
#pragma unroll
    for (int p = 0; p < 4; p++)
#pragma unroll
        for (int q = 0; q < 4; q++) acc2[p][q] = 0ull;

    for (int k0 = 0; k0 < HH; k0 += 16) {
        float4 a0 = *(const float4*)(arow + k0 + akk);
        float4 a1 = *(const float4*)(arow + k0 + akk + 4);
        float4 bv = *(const float4*)(wrow + k0);
        As[akk + 0][ar] = a0.x; As[akk + 1][ar] = a0.y; As[akk + 2][ar] = a0.z; As[akk + 3][ar] = a0.w;
        As[akk + 4][ar] = a1.x; As[akk + 5][ar] = a1.y; As[akk + 6][ar] = a1.z; As[akk + 7][ar] = a1.w;
        Bs[bkk + 0][br] = bv.x; Bs[bkk + 1][br] = bv.y; Bs[bkk + 2][br] = bv.z; Bs[bkk + 3][br] = bv.w;
        __syncthreads();
#pragma unroll
        for (int kk = 0; kk < 16; kk++) {
            ulonglong2 av0 = *(const ulonglong2*)&As[kk][tm * 8];
            ulonglong2 av1 = *(const ulonglong2*)&As[kk][tm * 8 + 4];
            float4 y = *(const float4*)&Bs[kk][tn * 4];
            u64 ap[4] = {av0.x, av0.y, av1.x, av1.y};
            u64 bd[4];
            PACK_F32X2(bd[0], y.x, y.x);
            PACK_F32X2(bd[1], y.y, y.y);
            PACK_F32X2(bd[2], y.z, y.z);
            PACK_F32X2(bd[3], y.w, y.w);
#pragma unroll
            for (int p = 0; p < 4; p++)
#pragma unroll
                for (int q = 0; q < 4; q++)
                    FMA_F32X2(acc2[p][q], ap[p], bd[q], acc2[p][q]);
        }
        __syncthreads();
    }

    // bias + stage tile into tbuf[row_local][col]
    const int colb = bn * 64 + tn * 4;
    float bsv[4];
#pragma unroll
    for (int q = 0; q < 4; q++) bsv[q] = b1[colb + q] + b2[colb + q];
#pragma unroll
    for (int p = 0; p < 4; p++) {
        float lo[4], hi[4];
#pragma unroll
        for (int q = 0; q < 4; q++) UNPACK_F32X2(lo[q], hi[q], acc2[p][q]);
        int r0 = tm * 8 + 2 * p;
#pragma unroll
        for (int q = 0; q < 4; q++) {
            tbuf[r0 * 65 + tn * 4 + q] = lo[q] + bsv[q];
            tbuf[(r0 + 1) * 65 + tn * 4 + q] = hi[q] + bsv[q];
        }
    }
    __syncthreads();

    // write out: gT[((t*4+g)*768 + j)*32 + b], coalesced over b
    const int g = bn / 12;
    const int j0 = (bn % 12) * 64;
#pragma unroll
    for (int tt = 0; tt < 4; tt++) {
        float* obase = gT + (((size_t)(bm * 4 + tt) * 4 + g) * 768 + j0) * 32;
#pragma unroll
        for (int k = 0; k < 8; k++) {
            int idx = k * 256 + tid;           // 0..2047
            int cc = idx >> 5, b = idx & 31;
            obase[cc * 32 + b] = tbuf[(tt * 32 + b) * 65 + cc];
        }
    }
}

// ---------------- Persistent LSTM layer (weights in SMEM, atomic barrier) ----------------
#define WS_FLOATS (3 * 4 * 768 * 2)                // 18432 floats = 73728 B
#define HS_FLOATS (768 * 33)                       // 25344 floats = 101376 B
#define EX_QWORDS (24 * 4 * 33)                    // 3168 u64 = 25344 B
#define SMEM_LSTM_BYTES ((WS_FLOATS + HS_FLOATS) * 4 + EX_QWORDS * 8)   // 200448 B

__global__ __launch_bounds__(768) void lstm_seq_k(float* __restrict__ hT)
{
    extern __shared__ float sm[];
    float* ws = sm;                                   // [jpl][g][k][2]
    float* hs = sm + WS_FLOATS;                       // hs[k*33 + b]
    u64* exq = (u64*)(sm + WS_FLOATS + HS_FLOATS);    // exq[(w*4+g)*33 + lane]
    const int tid = threadIdx.x;
    const int w = tid >> 5, lane = tid & 31;
    const int jpl = w >> 3, ks = w & 7;
    const int k0 = ks * 96;
    const bool act = (w < 6);
    const int ja = blockIdx.x * 6 + w;            // activation j (valid if act)
    const int jpa = w >> 1, jsel = w & 1;         // activation partial source
    float c = 0.f;

    // ---- one-time weight preload into smem
    {
        const float4* src4 = (const float4*)g_wpack;
        float4* dst4 = (float4*)ws;
#pragma unroll
        for (int it = 0; it < 6; it++) {
            int i = it * 768 + tid;         // 0..4607 float4s
            int chunk = i / 384;            // 0..11 = jpl*4+g
            int q = i - chunk * 384;
            int cjpl = chunk >> 2, cg = chunk & 3;
            dst4[chunk * 384 + q] = src4[(size_t)(cg * 384 + blockIdx.x * 3 + cjpl) * 384 + q];
        }
    }
    __syncthreads();

    const float* wbase = ws + (jpl * 4) * 1536 + k0 * 2;   // gate g at +g*1536

    for (int t = 0; t < SS; t++) {
        // prefetch preactivations for activation warps (coalesced)
        float pre[4];
        if (act) {
#pragma unroll
            for (int g = 0; g < 4; g++)
                pre[g] = g_gT[(((size_t)t * 4 + g) * HH + ja) * 32 + lane];
        }

        u64 accA[4], accB[4];
#pragma unroll
        for (int g = 0; g < 4; g++) { accA[g] = 0ull; accB[g] = 0ull; }

        if (t > 0) {
            // stage h_{t-1} from hT[t-1][j][b] into hs[k=j][b] (conflict-free scatter)
            const float* src = hT + (size_t)(t - 1) * HT_STRIDE;
#pragma unroll
            for (int r = 0; r < 8; r++) {
                int idx = r * 3072 + tid * 4;
                float4 v = __ldcg((const float4*)(src + idx));
                int jj = idx >> 5, b0 = idx & 31;
                hs[jj * 33 + b0 + 0] = v.x;
                hs[jj * 33 + b0 + 1] = v.y;
                hs[jj * 33 + b0 + 2] = v.z;
                hs[jj * 33 + b0 + 3] = v.w;
            }
            __syncthreads();

            const float* hb = hs + k0 * 33 + lane;
#pragma unroll 8
            for (int kc = 0; kc < 48; kc++) {
                float h0 = hb[(2 * kc) * 33];
                float h1 = hb[(2 * kc + 1) * 33];
                u64 hp0, hp1;
                PACK_F32X2(hp0, h0, h0);
                PACK_F32X2(hp1, h1, h1);
                ulonglong2 w0 = *(const ulonglong2*)(wbase + 0 * 1536 + kc * 4);
                ulonglong2 w1 = *(const ulonglong2*)(wbase + 1 * 1536 + kc * 4);
                ulonglong2 w2 = *(const ulonglong2*)(wbase + 2 * 1536 + kc * 4);
                ulonglong2 w3 = *(const ulonglong2*)(wbase + 3 * 1536 + kc * 4);
                FMA_F32X2(accA[0], w0.x, hp0, accA[0]); FMA_F32X2(accB[0], w0.y, hp1, accB[0]);
                FMA_F32X2(accA[1], w1.x, hp0, accA[1]); FMA_F32X2(accB[1], w1.y, hp1, accB[1]);
                FMA_F32X2(accA[2], w2.x, hp0, accA[2]); FMA_F32X2(accB[2], w2.y, hp1, accB[2]);
                FMA_F32X2(accA[3], w3.x, hp0, accA[3]); FMA_F32X2(accB[3], w3.y, hp1, accB[3]);
            }
        }
        // combine + exchange
#pragma unroll
        for (int g = 0; g < 4; g++) {
            u64 pd;
            ADD_F32X2(pd, accA[g], accB[g]);
            exq[(w * 4 + g) * 33 + lane] = pd;
        }
        __syncthreads();

        if (act) {
            float gt[4];
#pragma unroll
            for (int g = 0; g < 4; g++) {
                float s = pre[g];
#pragma unroll
                for (int p = 0; p < 8; p++) {
                    u64 v = exq[(((jpa * 8 + p) * 4) + g) * 33 + lane];
                    float lo, hi;
                    UNPACK_F32X2(lo, hi, v);
                    s += jsel ? hi : lo;
                }
                gt[g] = s;
            }
            float iv = __fdividef(1.f, 1.f + __expf(-gt[0]));
            float fv = __fdividef(1.f, 1.f + __expf(-gt[1]));
            float gv = tanhf(gt[2]);
            float ov = __fdividef(1.f, 1.f + __expf(-gt[3]));
            c = fv * c + iv * gv;
            float hn = ov * tanhf(c);
            hT[(size_t)t * HT_STRIDE + ja * 32 + lane] = hn;
        }

        if (t + 1 < SS) {
            __syncthreads();   // all h stores done (CTA-scope)
            if (tid == 0) {
                __threadfence();   // gpu-scope release (cumulative over bar.sync)
                atomicAdd(&g_bar, 1u);
                const unsigned target = (unsigned)(t + 1) * gridDim.x;
                while (*((volatile unsigned*)&g_bar) < target) __nanosleep(64);
            }
            __syncthreads();
        }
    }
}

// ---------------- transpose g_hT[t][j][b] -> h[n'=t*32+b][j] ----------------
__global__ __launch_bounds__(768) void transpose_h_k(
    const float* __restrict__ hT, float* __restrict__ hout)
{
    extern __shared__ float sm[];   // [768][33]
    const int t = blockIdx.x;
    const int tid = threadIdx.x;
#pragma unroll
    for (int r = 0; r < 32; r++) {
        int idx = r * 768 + tid;
        float v = __ldcg(hT + (size_t)t * HT_STRIDE + idx);
        sm[(idx >> 5) * 33 + (idx & 31)] = v;
    }
    __syncthreads();
#pragma unroll
    for (int b = 0; b < 32; b++) {
        hout[((size_t)(t * 32 + b)) * HH + tid] = sm[tid * 33 + b];
    }
}

// ---------------- logits + log_softmax (rows n' = t*32+b) ----------------
__global__ __launch_bounds__(256) void logits_k(
    const float* __restrict__ h, const float* __restrict__ Wout, const float* __restrict__ bout)
{
    const int warp = threadIdx.x >> 5, lane = threadIdx.x & 31;
    const int n = blockIdx.x * 8 + warp;   // n' = t*32 + b
    float a[24];
#pragma unroll
    for (int c = 0; c < 6; c++) {
        float4 v = *(const float4*)(h + (size_t)n * HH + c * 128 + lane * 4);
        a[c * 4 + 0] = v.x; a[c * 4 + 1] = v.y; a[c * 4 + 2] = v.z; a[c * 4 + 3] = v.w;
    }
    float lg[TT];
#pragma unroll
    for (int t = 0; t < TT; t++) {
        float s = 0.f;
#pragma unroll
        for (int c = 0; c < 6; c++) {
            float4 w = *(const float4*)(Wout + (size_t)t * HH + c * 128 + lane * 4);
            s = fmaf(w.x, a[c * 4 + 0], s); s = fmaf(w.y, a[c * 4 + 1], s);
            s = fmaf(w.z, a[c * 4 + 2], s); s = fmaf(w.w, a[c * 4 + 3], s);
        }
#pragma unroll
        for (int o = 16; o; o >>= 1) s += __shfl_xor_sync(0xffffffffu, s, o);
        lg[t] = s + bout[t];
    }
    float m = lg[0];
#pragma unroll
    for (int t = 1; t < TT; t++) m = fmaxf(m, lg[t]);
    float se = 0.f;
#pragma unroll
    for (int t = 0; t < TT; t++) se += __expf(lg[t] - m);
    float ls = m + __logf(se);
    if (lane < TT) {
        int b = n & 31, tstep = n >> 5;
        g_logp[((size_t)(b * SS + tstep)) * TT + lane] = lg[lane] - ls;
    }
}

// ---------------- CRF NLL forward (warp per batch) ----------------
__global__ __launch_bounds__(128) void crf_forward_k(
    const int* __restrict__ amask,
    const float* __restrict__ start_t, const float* __restrict__ end_t,
    const float* __restrict__ trans)
{
    __shared__ float ts[TT * TT];
    if (threadIdx.x < TT * TT) ts[threadIdx.x] = trans[threadIdx.x];
    __syncthreads();
    const int w = threadIdx.x >> 5, lane = threadIdx.x & 31;
    const int b = blockIdx.x * 4 + w;
    const int* tg = g_labels + b * SS;
    const int* mk = amask + b * SS;
    const float* em = g_logp + (size_t)b * SS * TT;

    int cnt = 0; float num = 0.f;
    for (int s = lane; s < SS; s += 32) {
        int m = mk[s]; cnt += m;
        if (s > 0 && m) num += ts[tg[s - 1] * TT + tg[s]] + em[s * TT + tg[s]];
    }
    if (lane == 0) num += start_t[tg[0]] + em[tg[0]];
#pragma unroll
    for (int o = 16; o; o >>= 1) {
        num += __shfl_xor_sync(0xffffffffu, num, o);
        cnt += __shfl_xor_sync(0xffffffffu, cnt, o);
    }
    if (lane == 0) num += end_t[tg[cnt - 1]];
    num = __shfl_sync(0xffffffffu, num, 0);

    const int j = lane;
    float score = (j < TT) ? start_t[j] + em[j] : -1e30f;
    for (int s = 1; s < SS; s++) {
        float v[TT];
#pragma unroll
        for (int i = 0; i < TT; i++) v[i] = __shfl_sync(0xffffffffu, score, i);
        if (mk[s]) {
            if (j < TT) {
                float vv[TT], m2 = -1e30f;
#pragma unroll
                for (int i = 0; i < TT; i++) { vv[i] = v[i] + ts[i * TT + j]; m2 = fmaxf(m2, vv[i]); }
                float ssum = 0.f;
#pragma unroll
                for (int i = 0; i < TT; i++) ssum += __expf(vv[i] - m2);
                score = m2 + __logf(ssum) + em[s * TT + j];
            }
        }
    }
    float sc2 = (j < TT) ? score + end_t[j] : -1e30f;
    float vv[TT];
#pragma unroll
    for (int i = 0; i < TT; i++) vv[i] = __shfl_sync(0xffffffffu, sc2, i);
    if (lane == 0) {
        float m2 = vv[0];
#pragma unroll
        for (int i = 1; i < TT; i++) m2 = fmaxf(m2, vv[i]);
        float ssum = 0.f;
#pragma unroll
        for (int i = 0; i < TT; i++) ssum += __expf(vv[i] - m2);
        float denom = m2 + __logf(ssum);
        g_llh[b] = num - denom;
        g_lenbuf[b] = cnt;
    }
}

// ---------------- Viterbi decode (warp per batch, bp in smem), float32 output ----------------
__global__ __launch_bounds__(128) void viterbi_k(
    const int* __restrict__ amask,
    const float* __restrict__ start_t, const float* __restrict__ end_t,
    const float* __restrict__ trans, float* __restrict__ outp, int navail)
{
    __shared__ float ts[TT * TT];
    __shared__ unsigned char bp[4][SS][TT];
    if (threadIdx.x < TT * TT) ts[threadIdx.x] = trans[threadIdx.x];
    __syncthreads();
    const int w = threadIdx.x >> 5, lane = threadIdx.x & 31;
    const int b = blockIdx.x * 4 + w;
    const int* mk = amask + b * SS;
    const float* em = g_logp + (size_t)b * SS * TT;
    const int j = lane;

    float score = (j < TT) ? start_t[j] + em[j] : -1e30f;
    for (int s = 1; s < SS; s++) {
        float v[TT];
#pragma unroll
        for (int i = 0; i < TT; i++) v[i] = __shfl_sync(0xffffffffu, score, i);
        if (j < TT) {
            int bi = j;
            if (mk[s]) {
                float best = v[0] + ts[0 * TT + j]; bi = 0;
#pragma unroll
                for (int i = 1; i < TT; i++) {
                    float cc = v[i] + ts[i * TT + j];
                    if (cc > best) { best = cc; bi = i; }
                }
                score = best + em[s * TT + j];
            }
            bp[w][s][j] = (unsigned char)bi;
        }
    }
    float sc2 = (j < TT) ? score + end_t[j] : -1e30f;
    float vv[TT];
#pragma unroll
    for (int i = 0; i < TT; i++) vv[i] = __shfl_sync(0xffffffffu, sc2, i);
    if (lane == 0) {
        int tag = 0; float best = vv[0];
#pragma unroll
        for (int i = 1; i < TT; i++) if (vv[i] > best) { best = vv[i]; tag = i; }
        for (int s = SS - 1; s >= 1; s--) {
            int idx = b * SS + s;
            if (idx < navail) outp[idx] = mk[s] ? (float)tag : 0.0f;
            tag = (int)bp[w][s][tag];
        }
        if (b * SS < navail) outp[b * SS] = mk[0] ? (float)tag : 0.0f;
    }
}

// ---------------- finalize loss (float32) ----------------
__global__ void finalize32_k(float* __restrict__ out) {
    const int lane = threadIdx.x;
    float llh = g_llh[lane];
    int len = g_lenbuf[lane];
#pragma unroll
    for (int o = 16; o; o >>= 1) {
        llh += __shfl_xor_sync(0xffffffffu, llh, o);
        len += __shfl_xor_sync(0xffffffffu, len, o);
    }
    if (lane == 0) out[0] = (float)(-(double)llh / (double)len);
}

// ---------------- launch ----------------
extern "C" void kernel_launch(void* const* d_in, const int* in_sizes, int n_in,
                              void* d_out, int out_size) {
    (void)in_sizes; (void)n_in;
    const void* ids    = d_in[0];
    const int*  amask  = (const int*)d_in[1];
    const void* labels = d_in[2];
    const float* emb   = (const float*)d_in[3];
    const float* Wih0  = (const float*)d_in[4];
    const float* Whh0  = (const float*)d_in[5];
    const float* bih0  = (const float*)d_in[6];
    const float* bhh0  = (const float*)d_in[7];
    const float* Wih1  = (const float*)d_in[8];
    const float* Whh1  = (const float*)d_in[9];
    const float* bih1  = (const float*)d_in[10];
    const float* bhh1  = (const float*)d_in[11];
    const float* Wout  = (const float*)d_in[12];
    const float* bout  = (const float*)d_in[13];
    const float* start_t = (const float*)d_in[14];
    const float* end_t   = (const float*)d_in[15];
    const float* trans   = (const float*)d_in[16];
    float* out = (float*)d_out;

    void *p_gT, *p_h0, *p_h1, *p_hT, *p_wp;
    cudaGetSymbolAddress(&p_gT, g_gT);
    cudaGetSymbolAddress(&p_h0, g_h0);
    cudaGetSymbolAddress(&p_h1, g_h1);
    cudaGetSymbolAddress(&p_hT, g_hT);
    cudaGetSymbolAddress(&p_wp, g_wpack);

    cudaFuncSetAttribute(lstm_seq_k, cudaFuncAttributeMaxDynamicSharedMemorySize, SMEM_LSTM_BYTES);
    const int tsm = 768 * 33 * 4;  // 101376
    cudaFuncSetAttribute(transpose_h_k, cudaFuncAttributeMaxDynamicSharedMemorySize, tsm);

    convert_idx_k<<<64, 256>>>(ids, labels);

    dim3 ggrid(48, 128);
    const int packblocks = (4 * 384 * 768 * 2 + 255) / 256;

    // layer 0 (sgemm writes gT layout directly)
    sgemm_gate_k<<<ggrid, 256>>>(emb, 1, Wih0, bih0, bhh0, (float*)p_gT);
    pack_whh_k<<<packblocks, 256>>>(Whh0, (float*)p_wp);
    reset_bar_k<<<1, 1>>>();
    lstm_seq_k<<<128, 768, SMEM_LSTM_BYTES>>>((float*)p_hT);
    transpose_h_k<<<512, 768, tsm>>>((const float*)p_hT, (float*)p_h0);
    // layer 1
    sgemm_gate_k<<<ggrid, 256>>>((const float*)p_h0, 0, Wih1, bih1, bhh1, (float*)p_gT);
    pack_whh_k<<<packblocks, 256>>>(Whh1, (float*)p_wp);
    reset_bar_k<<<1, 1>>>();
    lstm_seq_k<<<128, 768, SMEM_LSTM_BYTES>>>((float*)p_hT);
    transpose_h_k<<<512, 768, tsm>>>((const float*)p_hT, (float*)p_h1);

    logits_k<<<2048, 256>>>((const float*)p_h1, Wout, bout);
    crf_forward_k<<<8, 128>>>(amask, start_t, end_t, trans);

    if (out_size >= 1 + MTOT) {
        viterbi_k<<<8, 128>>>(amask, start_t, end_t, trans, out + 1, out_size - 1);
    }
    finalize32_k<<<1, 32>>>(out);
}